// round 13
// baseline (speedup 1.0000x reference)
#include <cuda_runtime.h>
#include <cuda_bf16.h>
#include <cstdint>

#define BB 4
#define TT 2048
#define DD 512
#define HH 8
#define HDD 64
#define LL 2
#define FFF 2048
#define ROWS (BB*TT)
#define NSEG (BB*(TT+1))
#define EPSF 1e-6f
#define ALPHAF 0.5f

// ---------------- scratch ----------------
__device__ float g_x [ROWS*DD];
__device__ float g_h [ROWS*DD];
__device__ float g_q [ROWS*DD];
__device__ float g_k [ROWS*DD];
__device__ float g_v [ROWS*DD];
__device__ float g_o [ROWS*DD];
__device__ float g_xn[ROWS*DD];
__device__ float g_f1[ROWS*FFF];
__device__ float g_f2[ROWS*FFF];
__device__ int   g_seg[ROWS];
__device__ float g_segsum[NSEG*DD];
__device__ float g_segcnt[NSEG];
// bf16 hi/lo planes for attention operands
__device__ __align__(16) __nv_bfloat16 g_qh[ROWS*DD], g_ql[ROWS*DD];
__device__ __align__(16) __nv_bfloat16 g_kh[ROWS*DD], g_kl[ROWS*DD];
__device__ __align__(16) __nv_bfloat16 g_vh[ROWS*DD], g_vl[ROWS*DD];

__constant__ unsigned int c_sepmask[8] = {
    0x00002600u, 0xFC00FFFFu, 0x78000001u, 0x78000000u, 0u, 0u, 0u, 0u
};

// ---------------- PTX helpers ----------------
__device__ __forceinline__ uint32_t sptr(const void* p) {
    return (uint32_t)__cvta_generic_to_shared(p);
}
#define LDM4(R, addr) \
    asm volatile("ldmatrix.sync.aligned.m8n8.x4.shared.b16 {%0,%1,%2,%3}, [%4];" \
        : "=r"((R)[0]), "=r"((R)[1]), "=r"((R)[2]), "=r"((R)[3]) : "r"(addr))
#define LDM4T(R, addr) \
    asm volatile("ldmatrix.sync.aligned.m8n8.x4.trans.shared.b16 {%0,%1,%2,%3}, [%4];" \
        : "=r"((R)[0]), "=r"((R)[1]), "=r"((R)[2]), "=r"((R)[3]) : "r"(addr))
#define CP16(dst, src) \
    asm volatile("cp.async.cg.shared.global [%0], [%1], 16;" :: "r"(dst), "l"(src))
#define CP_COMMIT asm volatile("cp.async.commit_group;")
#define CP_WAIT0  asm volatile("cp.async.wait_group 0;")
#define CP_WAIT1  asm volatile("cp.async.wait_group 1;")

__device__ __forceinline__ void mma_bf16(float* c, const uint32_t* a,
                                         uint32_t b0, uint32_t b1) {
    asm volatile(
        "mma.sync.aligned.m16n8k16.row.col.f32.bf16.bf16.f32 "
        "{%0,%1,%2,%3}, {%4,%5,%6,%7}, {%8,%9}, {%0,%1,%2,%3};"
        : "+f"(c[0]), "+f"(c[1]), "+f"(c[2]), "+f"(c[3])
        : "r"(a[0]), "r"(a[1]), "r"(a[2]), "r"(a[3]), "r"(b0), "r"(b1));
}

__device__ __forceinline__ void split_store(__nv_bfloat16* ph, __nv_bfloat16* pl,
                                            float4 t) {
    __nv_bfloat162 h01 = __floats2bfloat162_rn(t.x, t.y);
    __nv_bfloat162 h23 = __floats2bfloat162_rn(t.z, t.w);
    __nv_bfloat162 l01 = __floats2bfloat162_rn(t.x - __bfloat162float(h01.x),
                                               t.y - __bfloat162float(h01.y));
    __nv_bfloat162 l23 = __floats2bfloat162_rn(t.z - __bfloat162float(h23.x),
                                               t.w - __bfloat162float(h23.y));
    *(__nv_bfloat162*)(ph)     = h01;
    *(__nv_bfloat162*)(ph + 2) = h23;
    *(__nv_bfloat162*)(pl)     = l01;
    *(__nv_bfloat162*)(pl + 2) = l23;
}
__device__ __forceinline__ uint32_t pack_hi(float x, float y) {
    __nv_bfloat162 t = __floats2bfloat162_rn(x, y);
    return *(uint32_t*)&t;
}
__device__ __forceinline__ uint32_t pack_lo(float x, float y) {
    float xh = __bfloat162float(__float2bfloat16(x));
    float yh = __bfloat162float(__float2bfloat16(y));
    __nv_bfloat162 t = __floats2bfloat162_rn(x - xh, y - yh);
    return *(uint32_t*)&t;
}

// ---------------- embed ----------------
__global__ void embed_kernel(const int* __restrict__ tok,
                             const float* __restrict__ tab,
                             float* __restrict__ x) {
    int row = blockIdx.x;
    int t = tok[row]; t = min(max(t, 0), 255);
    ((float4*)(x + (size_t)row * DD))[threadIdx.x] =
        ((const float4*)(tab + (size_t)t * DD))[threadIdx.x];
}

// ---------------- rmsnorm ----------------
__global__ void rmsnorm_kernel(const float* __restrict__ x,
                               const float* __restrict__ w,
                               float* __restrict__ out) {
    int row = blockIdx.x;
    float4 v = ((const float4*)(x + (size_t)row * DD))[threadIdx.x];
    float ss = v.x*v.x + v.y*v.y + v.z*v.z + v.w*v.w;
    #pragma unroll
    for (int o = 16; o; o >>= 1) ss += __shfl_xor_sync(0xffffffffu, ss, o);
    __shared__ float sred[4];
    if ((threadIdx.x & 31) == 0) sred[threadIdx.x >> 5] = ss;
    __syncthreads();
    ss = sred[0] + sred[1] + sred[2] + sred[3];
    float r = rsqrtf(ss * (1.0f / DD) + EPSF);
    float4 wv = ((const float4*)w)[threadIdx.x];
    float4 o4;
    o4.x = v.x*r*wv.x; o4.y = v.y*r*wv.y; o4.z = v.z*r*wv.z; o4.w = v.w*r*wv.w;
    ((float4*)(out + (size_t)row * DD))[threadIdx.x] = o4;
}

// ---------------- bf16x3 GEMM, BK=32, dynamic smem double buffer ------------
// smem layout per buffer (bf16 units): Ah[128][40], Al[128][40],
// Bh[32][136], Bl[32][136]
#define AST32 40
#define BST32 136
#define APL32 (128*AST32)            /* 5120 */
#define BPL32 (32*BST32)             /* 4352 */
#define STG32 (2*APL32 + 2*BPL32)    /* 18944 bf16 */
#define GSMEM32 (2*STG32*2)          /* 75776 bytes */

template<bool ACCUM>
__device__ __forceinline__ void gemm32_body(
        const float* __restrict__ A, const float* __restrict__ B,
        float* __restrict__ C, int N, int K, int bx, int by) {
    extern __shared__ __nv_bfloat16 smg[];

    const int tid = threadIdx.x, lane = tid & 31, warp = tid >> 5;
    const int wm = (warp >> 2) * 64, wn = (warp & 3) * 32;
    const int g = lane >> 2, tg = lane & 3;
    const int lr = lane & 15, lc = lane >> 4;
    const int arow = tid >> 1, acol = (tid & 1) * 16;   // 16 floats per thread
    const int brow = tid >> 3, bcol = (tid & 7) * 16;   // 32 rows, 16 floats

    const float* Ag = A + ((size_t)by * 128 + arow) * K + acol;
    const float* Bg = B + bx * 128 + bcol;              // + (kt+brow)*N later
    float* Cb = C + ((size_t)by * 128) * N + bx * 128;

    float acc[4][4][4];
    #pragma unroll
    for (int i = 0; i < 4; i++)
        #pragma unroll
        for (int j = 0; j < 4; j++)
            #pragma unroll
            for (int r = 0; r < 4; r++) acc[i][j][r] = 0.f;

    float4 pa[4], pb[4];
    #pragma unroll
    for (int j = 0; j < 4; j++) {
        pa[j] = *(const float4*)(Ag + 4*j);
        pb[j] = *(const float4*)(Bg + (size_t)brow * N + 4*j);
    }
    {
        __nv_bfloat16* Ah = smg;
        __nv_bfloat16* Al = smg + APL32;
        __nv_bfloat16* Bh = smg + 2*APL32;
        __nv_bfloat16* Bl = Bh + BPL32;
        #pragma unroll
        for (int j = 0; j < 4; j++) {
            split_store(Ah + arow*AST32 + acol + 4*j,
                        Al + arow*AST32 + acol + 4*j, pa[j]);
            split_store(Bh + brow*BST32 + bcol + 4*j,
                        Bl + brow*BST32 + bcol + 4*j, pb[j]);
        }
    }

    int buf = 0;
    for (int kt = 0; kt < K; kt += 32) {
        __syncthreads();
        bool more = (kt + 32 < K);
        if (more) {
            #pragma unroll
            for (int j = 0; j < 4; j++) {
                pa[j] = *(const float4*)(Ag + kt + 32 + 4*j);
                pb[j] = *(const float4*)(Bg + (size_t)(kt + 32 + brow) * N + 4*j);
            }
        }
        {
            const __nv_bfloat16* Ah = smg + buf*STG32;
            const __nv_bfloat16* Al = Ah + APL32;
            const __nv_bfloat16* Bh = Ah + 2*APL32;
            const __nv_bfloat16* Bl = Bh + BPL32;
            #pragma unroll
            for (int ks = 0; ks < 2; ks++) {
                const int kof = ks * 16;
                uint32_t a_h[4][4], b_h[2][4];
                #pragma unroll
                for (int mi = 0; mi < 4; mi++)
                    LDM4(a_h[mi], sptr(Ah + (wm + mi*16 + lr)*AST32 + kof + 8*lc));
                #pragma unroll
                for (int p = 0; p < 2; p++)
                    LDM4T(b_h[p], sptr(Bh + (kof + lr)*BST32 + wn + p*16 + 8*lc));
                #pragma unroll
                for (int mi = 0; mi < 4; mi++)
                    #pragma unroll
                    for (int nj = 0; nj < 4; nj++)
                        mma_bf16(acc[mi][nj], a_h[mi],
                                 b_h[nj>>1][(nj&1)?2:0], b_h[nj>>1][(nj&1)?3:1]);
                uint32_t b_l[2][4];
                #pragma unroll
                for (int p = 0; p < 2; p++)
                    LDM4T(b_l[p], sptr(Bl + (kof + lr)*BST32 + wn + p*16 + 8*lc));
                #pragma unroll
                for (int mi = 0; mi < 4; mi++)
                    #pragma unroll
                    for (int nj = 0; nj < 4; nj++)
                        mma_bf16(acc[mi][nj], a_h[mi],
                                 b_l[nj>>1][(nj&1)?2:0], b_l[nj>>1][(nj&1)?3:1]);
                uint32_t a_l[4][4];
                #pragma unroll
                for (int mi = 0; mi < 4; mi++)
                    LDM4(a_l[mi], sptr(Al + (wm + mi*16 + lr)*AST32 + kof + 8*lc));
                #pragma unroll
                for (int mi = 0; mi < 4; mi++)
                    #pragma unroll
                    for (int nj = 0; nj < 4; nj++)
                        mma_bf16(acc[mi][nj], a_l[mi],
                                 b_h[nj>>1][(nj&1)?2:0], b_h[nj>>1][(nj&1)?3:1]);
            }
        }
        if (more) {
            __nv_bfloat16* Ah = smg + (buf ^ 1)*STG32;
            __nv_bfloat16* Al = Ah + APL32;
            __nv_bfloat16* Bh = Ah + 2*APL32;
            __nv_bfloat16* Bl = Bh + BPL32;
            #pragma unroll
            for (int j = 0; j < 4; j++) {
                split_store(Ah + arow*AST32 + acol + 4*j,
                            Al + arow*AST32 + acol + 4*j, pa[j]);
                split_store(Bh + brow*BST32 + bcol + 4*j,
                            Bl + brow*BST32 + bcol + 4*j, pb[j]);
            }
        }
        buf ^= 1;
    }

    #pragma unroll
    for (int mi = 0; mi < 4; mi++) {
        int r0 = wm + mi*16 + g;
        #pragma unroll
        for (int nj = 0; nj < 4; nj++) {
            int c = wn + nj*8 + 2*tg;
            float2* p0 = (float2*)(Cb + (size_t)r0 * N + c);
            float2* p1 = (float2*)(Cb + (size_t)(r0 + 8) * N + c);
            if (ACCUM) {
                float2 o0 = *p0, o1 = *p1;
                o0.x += acc[mi][nj][0]; o0.y += acc[mi][nj][1];
                o1.x += acc[mi][nj][2]; o1.y += acc[mi][nj][3];
                *p0 = o0; *p1 = o1;
            } else {
                *p0 = make_float2(acc[mi][nj][0], acc[mi][nj][1]);
                *p1 = make_float2(acc[mi][nj][2], acc[mi][nj][3]);
            }
        }
    }
}

template<bool ACCUM>
__global__ __launch_bounds__(256)
void gemm32_kernel(const float* __restrict__ A, const float* __restrict__ B,
                   float* __restrict__ C, int N, int K) {
    gemm32_body<ACCUM>(A, B, C, N, K, blockIdx.x, blockIdx.y);
}

template<int NM> struct MatSet { const float* B[NM]; float* C[NM]; };

template<int NM>
__global__ __launch_bounds__(256)
void gemm32m_kernel(const float* __restrict__ A, MatSet<NM> ms, int N, int K) {
    int ntile = N >> 7;
    int sel = blockIdx.x / ntile, bx = blockIdx.x % ntile;
    gemm32_body<false>(A, ms.B[sel], ms.C[sel], N, K, bx, blockIdx.y);
}

// ---------------- rope q/k (+q scale) + v convert -> hi/lo planes -----------
__global__ void ropecvt_kernel(const float* __restrict__ q,
                               const float* __restrict__ k,
                               const float* __restrict__ v,
                               __nv_bfloat16* __restrict__ qh, __nv_bfloat16* __restrict__ ql,
                               __nv_bfloat16* __restrict__ kh, __nv_bfloat16* __restrict__ kl,
                               __nv_bfloat16* __restrict__ vh, __nv_bfloat16* __restrict__ vl) {
    int row = blockIdx.x;
    int t = row & (TT - 1);
    int h = threadIdx.x >> 5, i = threadIdx.x & 31;
    size_t base = (size_t)row * DD + h * HDD;
    float f = (float)t * exp2f(-(float)i * 0.41524101186092437f);
    float s, c;
    sincosf(f, &s, &c);

    float qa = q[base + i], qb = q[base + i + 32];
    float r0 = (qa*c - qb*s) * 0.125f;
    float r1 = (qb*c + qa*s) * 0.125f;
    __nv_bfloat16 h0 = __float2bfloat16(r0), h1 = __float2bfloat16(r1);
    qh[base + i]      = h0; ql[base + i]      = __float2bfloat16(r0 - __bfloat162float(h0));
    qh[base + i + 32] = h1; ql[base + i + 32] = __float2bfloat16(r1 - __bfloat162float(h1));

    float ka = k[base + i], kb = k[base + i + 32];
    float s0 = ka*c - kb*s;
    float s1 = kb*c + ka*s;
    h0 = __float2bfloat16(s0); h1 = __float2bfloat16(s1);
    kh[base + i]      = h0; kl[base + i]      = __float2bfloat16(s0 - __bfloat162float(h0));
    kh[base + i + 32] = h1; kl[base + i + 32] = __float2bfloat16(s1 - __bfloat162float(h1));

    float va = v[base + i], vb = v[base + i + 32];
    h0 = __float2bfloat16(va); h1 = __float2bfloat16(vb);
    vh[base + i]      = h0; vl[base + i]      = __float2bfloat16(va - __bfloat162float(h0));
    vh[base + i + 32] = h1; vl[base + i + 32] = __float2bfloat16(vb - __bfloat162float(h1));
}

// ---------------- bf16x3 flash attention (R7 64-row version) ----------------
#define AS 72
#define APL (64*AS)
#define ATT_SMEM (8*APL*2)   /* 73728 bytes */

__global__ __launch_bounds__(128)
void attn_kernel(const __nv_bfloat16* __restrict__ qh, const __nv_bfloat16* __restrict__ ql,
                 const __nv_bfloat16* __restrict__ kh, const __nv_bfloat16* __restrict__ kl,
                 const __nv_bfloat16* __restrict__ vh, const __nv_bfloat16* __restrict__ vl,
                 float* __restrict__ o) {
    extern __shared__ __nv_bfloat16 smA[];

    const int tid = threadIdx.x, lane = tid & 31, warp = tid >> 5;
    const int g = lane >> 2, tg = lane & 3;
    const int lr = lane & 15, lc = lane >> 4;
    const int b = blockIdx.y >> 3, h = blockIdx.y & 7;
    const int q0 = blockIdx.x * 64;
    const int mrow = warp * 16;

    const __nv_bfloat16* qhg = qh + ((size_t)(b*TT + q0))*DD + h*64;
    const __nv_bfloat16* qlg = ql + ((size_t)(b*TT + q0))*DD + h*64;
    const __nv_bfloat16* khg = kh + ((size_t)(b*TT))*DD + h*64;
    const __nv_bfloat16* klg = kl + ((size_t)(b*TT))*DD + h*64;
    const __nv_bfloat16* vhg = vh + ((size_t)(b*TT))*DD + h*64;
    const __nv_bfloat16* vlg = vl + ((size_t)(b*TT))*DD + h*64;

    #pragma unroll
    for (int i = 0; i < 4; i++) {
        int idx = tid + 128*i;
        int r = idx >> 3, c = (idx & 7) * 8;
        CP16(sptr(smA + r*AS + c), qhg + (size_t)r*DD + c);
        CP16(sptr(smA + APL + r*AS + c), qlg + (size_t)r*DD + c);
    }
    CP_COMMIT; CP_WAIT0;
    __syncthreads();
    uint32_t qfh[4][4], qfl[4][4];
    #pragma unroll
    for (int c4 = 0; c4 < 4; c4++) {
        LDM4(qfh[c4], sptr(smA + (mrow + lr)*AS + c4*16 + 8*lc));
        LDM4(qfl[c4], sptr(smA + APL + (mrow + lr)*AS + c4*16 + 8*lc));
    }
    __syncthreads();

    #pragma unroll
    for (int i = 0; i < 4; i++) {
        int idx = tid + 128*i;
        int r = idx >> 3, c = (idx & 7) * 8;
        CP16(sptr(smA + 0*APL + r*AS + c), khg + (size_t)r*DD + c);
        CP16(sptr(smA + 1*APL + r*AS + c), klg + (size_t)r*DD + c);
        CP16(sptr(smA + 2*APL + r*AS + c), vhg + (size_t)r*DD + c);
        CP16(sptr(smA + 3*APL + r*AS + c), vlg + (size_t)r*DD + c);
    }
    CP_COMMIT;

    float oacc[8][4];
    #pragma unroll
    for (int n = 0; n < 8; n++)
        #pragma unroll
        for (int r = 0; r < 4; r++) oacc[n][r] = 0.f;
    float m0 = -1e30f, m1 = -1e30f, l0 = 0.f, l1 = 0.f;

    int buf = 0;
    for (int kt = 0; kt < TT; kt += 64) {
        bool more = (kt + 64 < TT);
        if (more) {
            int nb = buf ^ 1;
            #pragma unroll
            for (int i = 0; i < 4; i++) {
                int idx = tid + 128*i;
                int r = idx >> 3, c = (idx & 7) * 8;
                size_t go = (size_t)(kt + 64 + r)*DD + c;
                CP16(sptr(smA + (4*nb + 0)*APL + r*AS + c), khg + go);
                CP16(sptr(smA + (4*nb + 1)*APL + r*AS + c), klg + go);
                CP16(sptr(smA + (4*nb + 2)*APL + r*AS + c), vhg + go);
                CP16(sptr(smA + (4*nb + 3)*APL + r*AS + c), vlg + go);
            }
            CP_COMMIT;
            CP_WAIT1;
        } else {
            CP_WAIT0;
        }
        __syncthreads();

        const __nv_bfloat16* Kh = smA + (4*buf + 0)*APL;
        const __nv_bfloat16* Kl = smA + (4*buf + 1)*APL;
        const __nv_bfloat16* Vh = smA + (4*buf + 2)*APL;
        const __nv_bfloat16* Vl = smA + (4*buf + 3)*APL;

        float sfr[8][4];
        #pragma unroll
        for (int n = 0; n < 8; n++)
            #pragma unroll
            for (int r = 0; r < 4; r++) sfr[n][r] = 0.f;
        #pragma unroll
        for (int c4 = 0; c4 < 4; c4++) {
            #pragma unroll
            for (int p = 0; p < 4; p++) {
                uint32_t kh4[4], kl4[4];
                LDM4(kh4, sptr(Kh + (p*16 + lr)*AS + c4*16 + 8*lc));
                LDM4(kl4, sptr(Kl + (p*16 + lr)*AS + c4*16 + 8*lc));
                mma_bf16(sfr[2*p],   qfh[c4], kh4[0], kh4[2]);
                mma_bf16(sfr[2*p],   qfh[c4], kl4[0], kl4[2]);
                mma_bf16(sfr[2*p],   qfl[c4], kh4[0], kh4[2]);
                mma_bf16(sfr[2*p+1], qfh[c4], kh4[1], kh4[3]);
                mma_bf16(sfr[2*p+1], qfh[c4], kl4[1], kl4[3]);
                mma_bf16(sfr[2*p+1], qfl[c4], kh4[1], kh4[3]);
            }
        }

        float mx0 = -1e30f, mx1 = -1e30f;
        #pragma unroll
        for (int n = 0; n < 8; n++) {
            mx0 = fmaxf(mx0, fmaxf(sfr[n][0], sfr[n][1]));
            mx1 = fmaxf(mx1, fmaxf(sfr[n][2], sfr[n][3]));
        }
        mx0 = fmaxf(mx0, __shfl_xor_sync(0xffffffffu, mx0, 1));
        mx0 = fmaxf(mx0, __shfl_xor_sync(0xffffffffu, mx0, 2));
        mx1 = fmaxf(mx1, __shfl_xor_sync(0xffffffffu, mx1, 1));
        mx1 = fmaxf(mx1, __shfl_xor_sync(0xffffffffu, mx1, 2));
        float nm0 = fmaxf(m0, mx0), nm1 = fmaxf(m1, mx1);
        float cr0 = __expf(m0 - nm0), cr1 = __expf(m1 - nm1);
        m0 = nm0; m1 = nm1;
        l0 *= cr0; l1 *= cr1;
        #pragma unroll
        for (int n = 0; n < 8; n++) {
            sfr[n][0] = __expf(sfr[n][0] - m0);
            sfr[n][1] = __expf(sfr[n][1] - m0);
            sfr[n][2] = __expf(sfr[n][2] - m1);
            sfr[n][3] = __expf(sfr[n][3] - m1);
            l0 += sfr[n][0] + sfr[n][1];
            l1 += sfr[n][2] + sfr[n][3];
            oacc[n][0] *= cr0; oacc[n][1] *= cr0;
            oacc[n][2] *= cr1; oacc[n][3] *= cr1;
        }

        #pragma unroll
        for (int c4 = 0; c4 < 4; c4++) {
            uint32_t ph[4], pl[4];
            ph[0] = pack_hi(sfr[2*c4][0],   sfr[2*c4][1]);
            ph[1] = pack_hi(sfr[2*c4][2],   sfr[2*c4][3]);
            ph[2] = pack_hi(sfr[2*c4+1][0], sfr[2*c4+1][1]);
            ph[3] = pack_hi(sfr[2*c4+1][2], sfr[2*c4+1][3]);
            pl[0] = pack_lo(sfr[2*c4][0],   sfr[2*c4][1]);
            pl[1] = pack_lo(sfr[2*c4][2],   sfr[2*c4][3]);
            pl[2] = pack_lo(sfr[2*c4+1][0], sfr[2*c4+1][1]);
            pl[3] = pack_lo(sfr[2*c4+1][2], sfr[2*c4+1][3]);
            #pragma unroll
            for (int p = 0; p < 4; p++) {
                uint32_t vh4[4], vl4[4];
                LDM4T(vh4, sptr(Vh + (c4*16 + lr)*AS + p*16 + 8*lc));
                LDM4T(vl4, sptr(Vl + (c4*16 + lr)*AS + p*16 + 8*lc));
                mma_bf16(oacc[2*p],   ph, vh4[0], vh4[1]);
                mma_bf16(oacc[2*p],   ph, vl4[0], vl4[1]);
                mma_bf16(oacc[2*p],   pl, vh4[0], vh4[1]);
                mma_bf16(oacc[2*p+1], ph, vh4[2], vh4[3]);
                mma_bf16(oacc[2*p+1], ph, vl4[2], vl4[3]);
                mma_bf16(oacc[2*p+1], pl, vh4[2], vh4[3]);
            }
        }
        __syncthreads();
        buf ^= 1;
    }

    l0 += __shfl_xor_sync(0xffffffffu, l0, 1);
    l0 += __shfl_xor_sync(0xffffffffu, l0, 2);
    l1 += __shfl_xor_sync(0xffffffffu, l1, 1);
    l1 += __shfl_xor_sync(0xffffffffu, l1, 2);
    float inv0 = 1.f / l0, inv1 = 1.f / l1;

    int r0 = b*TT + q0 + mrow + g;
    #pragma unroll
    for (int nj = 0; nj < 8; nj++) {
        int c = h*64 + nj*8 + 2*tg;
        *(float2*)(o + (size_t)r0*DD + c) =
            make_float2(oacc[nj][0]*inv0, oacc[nj][1]*inv0);
        *(float2*)(o + (size_t)(r0+8)*DD + c) =
            make_float2(oacc[nj][2]*inv1, oacc[nj][3]*inv1);
    }
}

// ---------------- silu(f1)*f2 -> f1 ----------------
__global__ void silu_mul_kernel(float* __restrict__ f1,
                                const float* __restrict__ f2, int n4) {
    int i = blockIdx.x * blockDim.x + threadIdx.x;
    if (i < n4) {
        float4 a = ((float4*)f1)[i];
        float4 b = ((const float4*)f2)[i];
        a.x = a.x / (1.f + __expf(-a.x)) * b.x;
        a.y = a.y / (1.f + __expf(-a.y)) * b.y;
        a.z = a.z / (1.f + __expf(-a.z)) * b.z;
        a.w = a.w / (1.f + __expf(-a.w)) * b.w;
        ((float4*)f1)[i] = a;
    }
}

// ---------------- segment scan ----------------
__global__ void seg_scan_kernel(const int* __restrict__ tok,
                                int* __restrict__ seg) {
    int b = blockIdx.x;
    __shared__ int ssum[256];
    int t0 = threadIdx.x * 8;
    int loc[8];
    int run = 0;
    #pragma unroll
    for (int i = 0; i < 8; i++) {
        int tv = tok[b * TT + t0 + i];
        tv = min(max(tv, 0), 255);
        run += (int)((c_sepmask[tv >> 5] >> (tv & 31)) & 1u);
        loc[i] = run;
    }
    ssum[threadIdx.x] = run;
    __syncthreads();
    int val = run;
    for (int off = 1; off < 256; off <<= 1) {
        int add = (threadIdx.x >= off) ? ssum[threadIdx.x - off] : 0;
        __syncthreads();
        val += add;
        ssum[threadIdx.x] = val;
        __syncthreads();
    }
    int prefix = val - run;
    #pragma unroll
    for (int i = 0; i < 8; i++) seg[b * TT + t0 + i] = prefix + loc[i];
}

// ---------------- segment accumulate ----------------
__global__ void seg_acc_kernel(const float* __restrict__ xn,
                               const int* __restrict__ seg,
                               float* __restrict__ ssum,
                               float* __restrict__ scnt) {
    int row = blockIdx.x;
    int b = row >> 11;
    int s = seg[row] + b * (TT + 1);
    const float* xp = xn + (size_t)row * DD;
    float* sp = ssum + (size_t)s * DD;
    int i = threadIdx.x * 4;
    atomicAdd(&sp[i + 0], xp[i + 0]);
    atomicAdd(&sp[i + 1], xp[i + 1]);
    atomicAdd(&sp[i + 2], xp[i + 2]);
    atomicAdd(&sp[i + 3], xp[i + 3]);
    if (threadIdx.x == 0) atomicAdd(&scnt[s], 1.f);
}

// ---------------- final mix ----------------
__global__ void mix_kernel(const float* __restrict__ xn,
                           const int* __restrict__ seg,
                           const float* __restrict__ ssum,
                           const float* __restrict__ scnt,
                           float* __restrict__ out) {
    int row = blockIdx.x;
    int b = row >> 11;
    int s = seg[row] + b * (TT + 1);
    float cnt = fmaxf(scnt[s], 1.f);
    float w = (1.f - ALPHAF) / cnt;
    float4 xv = ((const float4*)(xn + (size_t)row * DD))[threadIdx.x];
    float4 sv = ((const float4*)(ssum + (size_t)s * DD))[threadIdx.x];
    float4 r;
    r.x = ALPHAF*xv.x + w*sv.x; r.y = ALPHAF*xv.y + w*sv.y;
    r.z = ALPHAF*xv.z + w*sv.z; r.w = ALPHAF*xv.w + w*sv.w;
    ((float4*)(out + (size_t)row * DD))[threadIdx.x] = r;
}

// ---------------- launch ----------------
extern "C" void kernel_launch(void* const* d_in, const int* in_sizes, int n_in,
                              void* d_out, int out_size) {
    const int*   tokens       = (const int*)  d_in[0];
    const float* embed_table  = (const float*)d_in[1];
    const float* attn_norm_w  = (const float*)d_in[2];
    const float* wq           = (const float*)d_in[3];
    const float* wk           = (const float*)d_in[4];
    const float* wv           = (const float*)d_in[5];
    const float* wo           = (const float*)d_in[6];
    const float* ffn_norm_w   = (const float*)d_in[7];
    const float* w1           = (const float*)d_in[8];
    const float* w2           = (const float*)d_in[9];
    const float* w3           = (const float*)d_in[10];
    const float* final_norm_w = (const float*)d_in[11];
    float* out = (float*)d_out;

    float *x, *h, *q, *k, *v, *o, *xn, *f1, *f2, *ssum, *scnt;
    int* seg;
    __nv_bfloat16 *qh, *ql, *kh, *kl, *vh, *vl;
    cudaGetSymbolAddress((void**)&x,   g_x);
    cudaGetSymbolAddress((void**)&h,   g_h);
    cudaGetSymbolAddress((void**)&q,   g_q);
    cudaGetSymbolAddress((void**)&k,   g_k);
    cudaGetSymbolAddress((void**)&v,   g_v);
    cudaGetSymbolAddress((void**)&o,   g_o);
    cudaGetSymbolAddress((void**)&xn,  g_xn);
    cudaGetSymbolAddress((void**)&f1,  g_f1);
    cudaGetSymbolAddress((void**)&f2,  g_f2);
    cudaGetSymbolAddress((void**)&seg, g_seg);
    cudaGetSymbolAddress((void**)&ssum, g_segsum);
    cudaGetSymbolAddress((void**)&scnt, g_segcnt);
    cudaGetSymbolAddress((void**)&qh, g_qh);
    cudaGetSymbolAddress((void**)&ql, g_ql);
    cudaGetSymbolAddress((void**)&kh, g_kh);
    cudaGetSymbolAddress((void**)&kl, g_kl);
    cudaGetSymbolAddress((void**)&vh, g_vh);
    cudaGetSymbolAddress((void**)&vl, g_vl);

    cudaFuncSetAttribute(attn_kernel,
                         cudaFuncAttributeMaxDynamicSharedMemorySize, ATT_SMEM);
    cudaFuncSetAttribute(gemm32_kernel<false>,
                         cudaFuncAttributeMaxDynamicSharedMemorySize, GSMEM32);
    cudaFuncSetAttribute(gemm32_kernel<true>,
                         cudaFuncAttributeMaxDynamicSharedMemorySize, GSMEM32);
    cudaFuncSetAttribute(gemm32m_kernel<2>,
                         cudaFuncAttributeMaxDynamicSharedMemorySize, GSMEM32);
    cudaFuncSetAttribute(gemm32m_kernel<3>,
                         cudaFuncAttributeMaxDynamicSharedMemorySize, GSMEM32);

    embed_kernel<<<ROWS, 128>>>(tokens, embed_table, x);

    dim3 gD  (DD  / 128, ROWS / 128);       // (4, 64)
    dim3 gQKV(3 * DD / 128, ROWS / 128);    // (12, 64)
    dim3 gW12(2 * FFF / 128, ROWS / 128);   // (32, 64)
    dim3 gAtt(TT / 64, BB * HH);            // (32, 32)

    for (int l = 0; l < LL; l++) {
        size_t oD = (size_t)l * DD * DD, oF = (size_t)l * DD * FFF;
        rmsnorm_kernel<<<ROWS, 128>>>(x, attn_norm_w + l*DD, h);

        MatSet<3> msqkv;
        msqkv.B[0] = wq + oD; msqkv.B[1] = wk + oD; msqkv.B[2] = wv + oD;
        msqkv.C[0] = q;       msqkv.C[1] = k;       msqkv.C[2] = v;
        gemm32m_kernel<3><<<gQKV, 256, GSMEM32>>>(h, msqkv, DD, DD);

        ropecvt_kernel<<<ROWS, 256>>>(q, k, v, qh, ql, kh, kl, vh, vl);
        attn_kernel<<<gAtt, 128, ATT_SMEM>>>(qh, ql, kh, kl, vh, vl, o);
        gemm32_kernel<true ><<<gD, 256, GSMEM32>>>(o, wo + oD, x, DD, DD);

        rmsnorm_kernel<<<ROWS, 128>>>(x, ffn_norm_w + l*DD, h);

        MatSet<2> msff;
        msff.B[0] = w1 + oF; msff.B[1] = w2 + oF;
        msff.C[0] = f1;      msff.C[1] = f2;
        gemm32m_kernel<2><<<gW12, 256, GSMEM32>>>(h, msff, FFF, DD);

        int n4 = ROWS * FFF / 4;
        silu_mul_kernel<<<(n4 + 255)/256, 256>>>(f1, f2, n4);
        gemm32_kernel<true ><<<gD, 256, GSMEM32>>>(f1, w3 + (size_t)l * FFF * DD, x, DD, FFF);
    }

    rmsnorm_kernel<<<ROWS, 128>>>(x, final_norm_w, xn);

    cudaMemsetAsync(ssum, 0, sizeof(float) * (size_t)NSEG * DD);
    cudaMemsetAsync(scnt, 0, sizeof(float) * NSEG);
    seg_scan_kernel<<<BB, 256>>>(tokens, seg);
    seg_acc_kernel<<<ROWS, 128>>>(xn, seg, ssum, scnt);
    mix_kernel<<<ROWS, 128>>>(xn, seg, ssum, scnt, out);
}

// round 15
// speedup vs baseline: 1.1601x; 1.1601x over previous
#include <cuda_runtime.h>
#include <cuda_bf16.h>
#include <cstdint>

#define BB 4
#define TT 2048
#define DD 512
#define HH 8
#define HDD 64
#define LL 2
#define FFF 2048
#define ROWS (BB*TT)
#define NSEG (BB*(TT+1))
#define EPSF 1e-6f
#define ALPHAF 0.5f

// ---------------- scratch ----------------
__device__ float g_x [ROWS*DD];
__device__ float g_h [ROWS*DD];
__device__ float g_q [ROWS*DD];
__device__ float g_k [ROWS*DD];
__device__ float g_o [ROWS*DD];
__device__ float g_xn[ROWS*DD];
__device__ float g_f1[ROWS*FFF];
__device__ float g_f2[ROWS*FFF];
__device__ int   g_seg[ROWS];
__device__ float g_segsum[NSEG*DD];
__device__ float g_segcnt[NSEG];
// bf16 hi/lo planes for attention operands
__device__ __align__(16) __nv_bfloat16 g_qh[ROWS*DD], g_ql[ROWS*DD];
__device__ __align__(16) __nv_bfloat16 g_kh[ROWS*DD], g_kl[ROWS*DD];
__device__ __align__(16) __nv_bfloat16 g_vh[ROWS*DD], g_vl[ROWS*DD];

__constant__ unsigned int c_sepmask[8] = {
    0x00002600u, 0xFC00FFFFu, 0x78000001u, 0x78000000u, 0u, 0u, 0u, 0u
};

// ---------------- PTX helpers ----------------
__device__ __forceinline__ uint32_t sptr(const void* p) {
    return (uint32_t)__cvta_generic_to_shared(p);
}
#define LDM4(R, addr) \
    asm volatile("ldmatrix.sync.aligned.m8n8.x4.shared.b16 {%0,%1,%2,%3}, [%4];" \
        : "=r"((R)[0]), "=r"((R)[1]), "=r"((R)[2]), "=r"((R)[3]) : "r"(addr))
#define LDM4T(R, addr) \
    asm volatile("ldmatrix.sync.aligned.m8n8.x4.trans.shared.b16 {%0,%1,%2,%3}, [%4];" \
        : "=r"((R)[0]), "=r"((R)[1]), "=r"((R)[2]), "=r"((R)[3]) : "r"(addr))
#define CP16(dst, src) \
    asm volatile("cp.async.cg.shared.global [%0], [%1], 16;" :: "r"(dst), "l"(src))
#define CP_COMMIT asm volatile("cp.async.commit_group;")
#define CP_WAIT0  asm volatile("cp.async.wait_group 0;")
#define CP_WAIT1  asm volatile("cp.async.wait_group 1;")

__device__ __forceinline__ void mma_bf16(float* c, const uint32_t* a,
                                         uint32_t b0, uint32_t b1) {
    asm volatile(
        "mma.sync.aligned.m16n8k16.row.col.f32.bf16.bf16.f32 "
        "{%0,%1,%2,%3}, {%4,%5,%6,%7}, {%8,%9}, {%0,%1,%2,%3};"
        : "+f"(c[0]), "+f"(c[1]), "+f"(c[2]), "+f"(c[3])
        : "r"(a[0]), "r"(a[1]), "r"(a[2]), "r"(a[3]), "r"(b0), "r"(b1));
}

__device__ __forceinline__ void split_store(__nv_bfloat16* ph, __nv_bfloat16* pl,
                                            float4 t) {
    __nv_bfloat162 h01 = __floats2bfloat162_rn(t.x, t.y);
    __nv_bfloat162 h23 = __floats2bfloat162_rn(t.z, t.w);
    __nv_bfloat162 l01 = __floats2bfloat162_rn(t.x - __bfloat162float(h01.x),
                                               t.y - __bfloat162float(h01.y));
    __nv_bfloat162 l23 = __floats2bfloat162_rn(t.z - __bfloat162float(h23.x),
                                               t.w - __bfloat162float(h23.y));
    *(__nv_bfloat162*)(ph)     = h01;
    *(__nv_bfloat162*)(ph + 2) = h23;
    *(__nv_bfloat162*)(pl)     = l01;
    *(__nv_bfloat162*)(pl + 2) = l23;
}
__device__ __forceinline__ uint32_t pack_hi(float x, float y) {
    __nv_bfloat162 t = __floats2bfloat162_rn(x, y);
    return *(uint32_t*)&t;
}
__device__ __forceinline__ uint32_t pack_lo(float x, float y) {
    float xh = __bfloat162float(__float2bfloat16(x));
    float yh = __bfloat162float(__float2bfloat16(y));
    __nv_bfloat162 t = __floats2bfloat162_rn(x - xh, y - yh);
    return *(uint32_t*)&t;
}

// ---------------- embed ----------------
__global__ void embed_kernel(const int* __restrict__ tok,
                             const float* __restrict__ tab,
                             float* __restrict__ x) {
    int row = blockIdx.x;
    int t = tok[row]; t = min(max(t, 0), 255);
    ((float4*)(x + (size_t)row * DD))[threadIdx.x] =
        ((const float4*)(tab + (size_t)t * DD))[threadIdx.x];
}

// ---------------- rmsnorm ----------------
__global__ void rmsnorm_kernel(const float* __restrict__ x,
                               const float* __restrict__ w,
                               float* __restrict__ out) {
    int row = blockIdx.x;
    float4 v = ((const float4*)(x + (size_t)row * DD))[threadIdx.x];
    float ss = v.x*v.x + v.y*v.y + v.z*v.z + v.w*v.w;
    #pragma unroll
    for (int o = 16; o; o >>= 1) ss += __shfl_xor_sync(0xffffffffu, ss, o);
    __shared__ float sred[4];
    if ((threadIdx.x & 31) == 0) sred[threadIdx.x >> 5] = ss;
    __syncthreads();
    ss = sred[0] + sred[1] + sred[2] + sred[3];
    float r = rsqrtf(ss * (1.0f / DD) + EPSF);
    float4 wv = ((const float4*)w)[threadIdx.x];
    float4 o4;
    o4.x = v.x*r*wv.x; o4.y = v.y*r*wv.y; o4.z = v.z*r*wv.z; o4.w = v.w*r*wv.w;
    ((float4*)(out + (size_t)row * DD))[threadIdx.x] = o4;
}

// ---------------- bf16x3 GEMM body (R4/R7 proven), runtime epilogue select --
// plane_out == false: fp32 C (store or accum per ACCUM)
// plane_out == true : bf16 hi/lo plane output (Ph/Pl)
#define AST 24
#define BST 136

template<bool ACCUM>
__device__ __forceinline__ void gemm3_body(
        const float* __restrict__ A, const float* __restrict__ B,
        float* __restrict__ C,
        __nv_bfloat16* __restrict__ Ph, __nv_bfloat16* __restrict__ Pl,
        bool plane_out, int N, int K, int bx, int by) {
    __shared__ __nv_bfloat16 sAh[2][128][AST];
    __shared__ __nv_bfloat16 sAl[2][128][AST];
    __shared__ __nv_bfloat16 sBh[2][16][BST];
    __shared__ __nv_bfloat16 sBl[2][16][BST];

    const int tid = threadIdx.x, lane = tid & 31, warp = tid >> 5;
    const int wm = (warp >> 2) * 64, wn = (warp & 3) * 32;
    const int g = lane >> 2, tg = lane & 3;
    const int lr = lane & 15, lc = lane >> 4;
    const int arow = tid >> 1, acol = (tid & 1) * 8;
    const int brow = tid >> 4, bcol = (tid & 15) * 8;

    const float* Ag = A + ((size_t)by * 128 + arow) * K + acol;
    const float* Bg = B + (size_t)brow * N + bx * 128 + bcol;

    float acc[4][4][4];
    #pragma unroll
    for (int i = 0; i < 4; i++)
        #pragma unroll
        for (int j = 0; j < 4; j++)
            #pragma unroll
            for (int r = 0; r < 4; r++) acc[i][j][r] = 0.f;

    float4 pa0 = *(const float4*)(Ag);
    float4 pa1 = *(const float4*)(Ag + 4);
    float4 pb0 = *(const float4*)(Bg);
    float4 pb1 = *(const float4*)(Bg + 4);
    split_store(&sAh[0][arow][acol],   &sAl[0][arow][acol],   pa0);
    split_store(&sAh[0][arow][acol+4], &sAl[0][arow][acol+4], pa1);
    split_store(&sBh[0][brow][bcol],   &sBl[0][brow][bcol],   pb0);
    split_store(&sBh[0][brow][bcol+4], &sBl[0][brow][bcol+4], pb1);

    int buf = 0;
    for (int kt = 0; kt < K; kt += 16) {
        __syncthreads();
        bool more = (kt + 16 < K);
        if (more) {
            pa0 = *(const float4*)(Ag + kt + 16);
            pa1 = *(const float4*)(Ag + kt + 20);
            pb0 = *(const float4*)(Bg + (size_t)(kt + 16) * N);
            pb1 = *(const float4*)(Bg + (size_t)(kt + 16) * N + 4);
        }
        {
            const __nv_bfloat16* Ah = &sAh[buf][0][0];
            const __nv_bfloat16* Al = &sAl[buf][0][0];
            const __nv_bfloat16* Bh = &sBh[buf][0][0];
            const __nv_bfloat16* Bl = &sBl[buf][0][0];
            uint32_t a_h[4][4], b_h[2][4];
            #pragma unroll
            for (int mi = 0; mi < 4; mi++)
                LDM4(a_h[mi], sptr(Ah + (wm + mi*16 + lr)*AST + 8*lc));
            #pragma unroll
            for (int p = 0; p < 2; p++)
                LDM4T(b_h[p], sptr(Bh + lr*BST + wn + p*16 + 8*lc));
            #pragma unroll
            for (int mi = 0; mi < 4; mi++)
                #pragma unroll
                for (int nj = 0; nj < 4; nj++)
                    mma_bf16(acc[mi][nj], a_h[mi],
                             b_h[nj>>1][(nj&1)?2:0], b_h[nj>>1][(nj&1)?3:1]);
            uint32_t b_l[2][4];
            #pragma unroll
            for (int p = 0; p < 2; p++)
                LDM4T(b_l[p], sptr(Bl + lr*BST + wn + p*16 + 8*lc));
            #pragma unroll
            for (int mi = 0; mi < 4; mi++)
                #pragma unroll
                for (int nj = 0; nj < 4; nj++)
                    mma_bf16(acc[mi][nj], a_h[mi],
                             b_l[nj>>1][(nj&1)?2:0], b_l[nj>>1][(nj&1)?3:1]);
            uint32_t a_l[4][4];
            #pragma unroll
            for (int mi = 0; mi < 4; mi++)
                LDM4(a_l[mi], sptr(Al + (wm + mi*16 + lr)*AST + 8*lc));
            #pragma unroll
            for (int mi = 0; mi < 4; mi++)
                #pragma unroll
                for (int nj = 0; nj < 4; nj++)
                    mma_bf16(acc[mi][nj], a_l[mi],
                             b_h[nj>>1][(nj&1)?2:0], b_h[nj>>1][(nj&1)?3:1]);
        }
        if (more) {
            int nb = buf ^ 1;
            split_store(&sAh[nb][arow][acol],   &sAl[nb][arow][acol],   pa0);
            split_store(&sAh[nb][arow][acol+4], &sAl[nb][arow][acol+4], pa1);
            split_store(&sBh[nb][brow][bcol],   &sBl[nb][brow][bcol],   pb0);
            split_store(&sBh[nb][brow][bcol+4], &sBl[nb][brow][bcol+4], pb1);
        }
        buf ^= 1;
    }

    if (!plane_out) {
        float* Cb = C + ((size_t)by * 128) * N + bx * 128;
        #pragma unroll
        for (int mi = 0; mi < 4; mi++) {
            int r0 = wm + mi*16 + g;
            #pragma unroll
            for (int nj = 0; nj < 4; nj++) {
                int c = wn + nj*8 + 2*tg;
                float2* p0 = (float2*)(Cb + (size_t)r0 * N + c);
                float2* p1 = (float2*)(Cb + (size_t)(r0 + 8) * N + c);
                if (ACCUM) {
                    float2 o0 = *p0, o1 = *p1;
                    o0.x += acc[mi][nj][0]; o0.y += acc[mi][nj][1];
                    o1.x += acc[mi][nj][2]; o1.y += acc[mi][nj][3];
                    *p0 = o0; *p1 = o1;
                } else {
                    *p0 = make_float2(acc[mi][nj][0], acc[mi][nj][1]);
                    *p1 = make_float2(acc[mi][nj][2], acc[mi][nj][3]);
                }
            }
        }
    } else {
        __nv_bfloat16* PhB = Ph + ((size_t)by * 128) * N + bx * 128;
        __nv_bfloat16* PlB = Pl + ((size_t)by * 128) * N + bx * 128;
        #pragma unroll
        for (int mi = 0; mi < 4; mi++) {
            int r0 = wm + mi*16 + g;
            #pragma unroll
            for (int nj = 0; nj < 4; nj++) {
                int c = wn + nj*8 + 2*tg;
                *(uint32_t*)(PhB + (size_t)r0 * N + c) =
                    pack_hi(acc[mi][nj][0], acc[mi][nj][1]);
                *(uint32_t*)(PlB + (size_t)r0 * N + c) =
                    pack_lo(acc[mi][nj][0], acc[mi][nj][1]);
                *(uint32_t*)(PhB + (size_t)(r0 + 8) * N + c) =
                    pack_hi(acc[mi][nj][2], acc[mi][nj][3]);
                *(uint32_t*)(PlB + (size_t)(r0 + 8) * N + c) =
                    pack_lo(acc[mi][nj][2], acc[mi][nj][3]);
            }
        }
    }
}

template<bool ACCUM>
__global__ __launch_bounds__(256)
void gemm3_kernel(const float* __restrict__ A, const float* __restrict__ B,
                  float* __restrict__ C, int N, int K) {
    gemm3_body<ACCUM>(A, B, C, nullptr, nullptr, false, N, K,
                      blockIdx.x, blockIdx.y);
}

template<int NM> struct MatSet { const float* B[NM]; float* C[NM]; };

// fused QKV: sel 0,1 -> fp32 q/k; sel 2 -> bf16 hi/lo planes (V, no rope)
__global__ __launch_bounds__(256)
void gemm3qkv_kernel(const float* __restrict__ A, MatSet<3> ms,
                     __nv_bfloat16* __restrict__ vh,
                     __nv_bfloat16* __restrict__ vl, int N, int K) {
    int ntile = N >> 7;
    int sel = blockIdx.x / ntile, bx = blockIdx.x % ntile;
    bool plane = (sel == 2);
    gemm3_body<false>(A, ms.B[sel], plane ? nullptr : ms.C[sel],
                      vh, vl, plane, N, K, bx, blockIdx.y);
}

template<int NM>
__global__ __launch_bounds__(256)
void gemm3m_kernel(const float* __restrict__ A, MatSet<NM> ms, int N, int K) {
    int ntile = N >> 7;
    int sel = blockIdx.x / ntile, bx = blockIdx.x % ntile;
    gemm3_body<false>(A, ms.B[sel], ms.C[sel], nullptr, nullptr, false,
                      N, K, bx, blockIdx.y);
}

// ---------------- rope q/k (+q scale) -> hi/lo planes (v handled in GEMM) ---
__global__ void ropecvt_kernel(const float* __restrict__ q,
                               const float* __restrict__ k,
                               __nv_bfloat16* __restrict__ qh, __nv_bfloat16* __restrict__ ql,
                               __nv_bfloat16* __restrict__ kh, __nv_bfloat16* __restrict__ kl) {
    int row = blockIdx.x;
    int t = row & (TT - 1);
    int h = threadIdx.x >> 5, i = threadIdx.x & 31;
    size_t base = (size_t)row * DD + h * HDD;
    float f = (float)t * exp2f(-(float)i * 0.41524101186092437f);
    float s, c;
    sincosf(f, &s, &c);

    float qa = q[base + i], qb = q[base + i + 32];
    float r0 = (qa*c - qb*s) * 0.125f;
    float r1 = (qb*c + qa*s) * 0.125f;
    __nv_bfloat16 h0 = __float2bfloat16(r0), h1 = __float2bfloat16(r1);
    qh[base + i]      = h0; ql[base + i]      = __float2bfloat16(r0 - __bfloat162float(h0));
    qh[base + i + 32] = h1; ql[base + i + 32] = __float2bfloat16(r1 - __bfloat162float(h1));

    float ka = k[base + i], kb = k[base + i + 32];
    float s0 = ka*c - kb*s;
    float s1 = kb*c + ka*s;
    h0 = __float2bfloat16(s0); h1 = __float2bfloat16(s1);
    kh[base + i]      = h0; kl[base + i]      = __float2bfloat16(s0 - __bfloat162float(h0));
    kh[base + i + 32] = h1; kl[base + i + 32] = __float2bfloat16(s1 - __bfloat162float(h1));
}

// ---------------- bf16x3 flash attention (R7 64-row version) ----------------
#define AS 72
#define APL (64*AS)
#define ATT_SMEM (8*APL*2)   /* 73728 bytes */

__global__ __launch_bounds__(128)
void attn_kernel(const __nv_bfloat16* __restrict__ qh, const __nv_bfloat16* __restrict__ ql,
                 const __nv_bfloat16* __restrict__ kh, const __nv_bfloat16* __restrict__ kl,
                 const __nv_bfloat16* __restrict__ vh, const __nv_bfloat16* __restrict__ vl,
                 float* __restrict__ o) {
    extern __shared__ __nv_bfloat16 smA[];

    const int tid = threadIdx.x, lane = tid & 31, warp = tid >> 5;
    const int g = lane >> 2, tg = lane & 3;
    const int lr = lane & 15, lc = lane >> 4;
    const int b = blockIdx.y >> 3, h = blockIdx.y & 7;
    const int q0 = blockIdx.x * 64;
    const int mrow = warp * 16;

    const __nv_bfloat16* qhg = qh + ((size_t)(b*TT + q0))*DD + h*64;
    const __nv_bfloat16* qlg = ql + ((size_t)(b*TT + q0))*DD + h*64;
    const __nv_bfloat16* khg = kh + ((size_t)(b*TT))*DD + h*64;
    const __nv_bfloat16* klg = kl + ((size_t)(b*TT))*DD + h*64;
    const __nv_bfloat16* vhg = vh + ((size_t)(b*TT))*DD + h*64;
    const __nv_bfloat16* vlg = vl + ((size_t)(b*TT))*DD + h*64;

    #pragma unroll
    for (int i = 0; i < 4; i++) {
        int idx = tid + 128*i;
        int r = idx >> 3, c = (idx & 7) * 8;
        CP16(sptr(smA + r*AS + c), qhg + (size_t)r*DD + c);
        CP16(sptr(smA + APL + r*AS + c), qlg + (size_t)r*DD + c);
    }
    CP_COMMIT; CP_WAIT0;
    __syncthreads();
    uint32_t qfh[4][4], qfl[4][4];
    #pragma unroll
    for (int c4 = 0; c4 < 4; c4++) {
        LDM4(qfh[c4], sptr(smA + (mrow + lr)*AS + c4*16 + 8*lc));
        LDM4(qfl[c4], sptr(smA + APL + (mrow + lr)*AS + c4*16 + 8*lc));
    }
    __syncthreads();

    #pragma unroll
    for (int i = 0; i < 4; i++) {
        int idx = tid + 128*i;
        int r = idx >> 3, c = (idx & 7) * 8;
        CP16(sptr(smA + 0*APL + r*AS + c), khg + (size_t)r*DD + c);
        CP16(sptr(smA + 1*APL + r*AS + c), klg + (size_t)r*DD + c);
        CP16(sptr(smA + 2*APL + r*AS + c), vhg + (size_t)r*DD + c);
        CP16(sptr(smA + 3*APL + r*AS + c), vlg + (size_t)r*DD + c);
    }
    CP_COMMIT;

    float oacc[8][4];
    #pragma unroll
    for (int n = 0; n < 8; n++)
        #pragma unroll
        for (int r = 0; r < 4; r++) oacc[n][r] = 0.f;
    float m0 = -1e30f, m1 = -1e30f, l0 = 0.f, l1 = 0.f;

    int buf = 0;
    for (int kt = 0; kt < TT; kt += 64) {
        bool more = (kt + 64 < TT);
        if (more) {
            int nb = buf ^ 1;
            #pragma unroll
            for (int i = 0; i < 4; i++) {
                int idx = tid + 128*i;
                int r = idx >> 3, c = (idx & 7) * 8;
                size_t go = (size_t)(kt + 64 + r)*DD + c;
                CP16(sptr(smA + (4*nb + 0)*APL + r*AS + c), khg + go);
                CP16(sptr(smA + (4*nb + 1)*APL + r*AS + c), klg + go);
                CP16(sptr(smA + (4*nb + 2)*APL + r*AS + c), vhg + go);
                CP16(sptr(smA + (4*nb + 3)*APL + r*AS + c), vlg + go);
            }
            CP_COMMIT;
            CP_WAIT1;
        } else {
            CP_WAIT0;
        }
        __syncthreads();

        const __nv_bfloat16* Kh = smA + (4*buf + 0)*APL;
        const __nv_bfloat16* Kl = smA + (4*buf + 1)*APL;
        const __nv_bfloat16* Vh = smA + (4*buf + 2)*APL;
        const __nv_bfloat16* Vl = smA + (4*buf + 3)*APL;

        float sfr[8][4];
        #pragma unroll
        for (int n = 0; n < 8; n++)
            #pragma unroll
            for (int r = 0; r < 4; r++) sfr[n][r] = 0.f;
        #pragma unroll
        for (int c4 = 0; c4 < 4; c4++) {
            #pragma unroll
            for (int p = 0; p < 4; p++) {
                uint32_t kh4[4], kl4[4];
                LDM4(kh4, sptr(Kh + (p*16 + lr)*AS + c4*16 + 8*lc));
                LDM4(kl4, sptr(Kl + (p*16 + lr)*AS + c4*16 + 8*lc));
                mma_bf16(sfr[2*p],   qfh[c4], kh4[0], kh4[2]);
                mma_bf16(sfr[2*p],   qfh[c4], kl4[0], kl4[2]);
                mma_bf16(sfr[2*p],   qfl[c4], kh4[0], kh4[2]);
                mma_bf16(sfr[2*p+1], qfh[c4], kh4[1], kh4[3]);
                mma_bf16(sfr[2*p+1], qfh[c4], kl4[1], kl4[3]);
                mma_bf16(sfr[2*p+1], qfl[c4], kh4[1], kh4[3]);
            }
        }

        float mx0 = -1e30f, mx1 = -1e30f;
        #pragma unroll
        for (int n = 0; n < 8; n++) {
            mx0 = fmaxf(mx0, fmaxf(sfr[n][0], sfr[n][1]));
            mx1 = fmaxf(mx1, fmaxf(sfr[n][2], sfr[n][3]));
        }
        mx0 = fmaxf(mx0, __shfl_xor_sync(0xffffffffu, mx0, 1));
        mx0 = fmaxf(mx0, __shfl_xor_sync(0xffffffffu, mx0, 2));
        mx1 = fmaxf(mx1, __shfl_xor_sync(0xffffffffu, mx1, 1));
        mx1 = fmaxf(mx1, __shfl_xor_sync(0xffffffffu, mx1, 2));
        float nm0 = fmaxf(m0, mx0), nm1 = fmaxf(m1, mx1);
        float cr0 = __expf(m0 - nm0), cr1 = __expf(m1 - nm1);
        m0 = nm0; m1 = nm1;
        l0 *= cr0; l1 *= cr1;
        #pragma unroll
        for (int n = 0; n < 8; n++) {
            sfr[n][0] = __expf(sfr[n][0] - m0);
            sfr[n][1] = __expf(sfr[n][1] - m0);
            sfr[n][2] = __expf(sfr[n][2] - m1);
            sfr[n][3] = __expf(sfr[n][3] - m1);
            l0 += sfr[n][0] + sfr[n][1];
            l1 += sfr[n][2] + sfr[n][3];
            oacc[n][0] *= cr0; oacc[n][1] *= cr0;
            oacc[n][2] *= cr1; oacc[n][3] *= cr1;
        }

        #pragma unroll
        for (int c4 = 0; c4 < 4; c4++) {
            uint32_t ph[4], pl[4];
            ph[0] = pack_hi(sfr[2*c4][0],   sfr[2*c4][1]);
            ph[1] = pack_hi(sfr[2*c4][2],   sfr[2*c4][3]);
            ph[2] = pack_hi(sfr[2*c4+1][0], sfr[2*c4+1][1]);
            ph[3] = pack_hi(sfr[2*c4+1][2], sfr[2*c4+1][3]);
            pl[0] = pack_lo(sfr[2*c4][0],   sfr[2*c4][1]);
            pl[1] = pack_lo(sfr[2*c4][2],   sfr[2*c4][3]);
            pl[2] = pack_lo(sfr[2*c4+1][0], sfr[2*c4+1][1]);
            pl[3] = pack_lo(sfr[2*c4+1][2], sfr[2*c4+1][3]);
            #pragma unroll
            for (int p = 0; p < 4; p++) {
                uint32_t vh4[4], vl4[4];
                LDM4T(vh4, sptr(Vh + (c4*16 + lr)*AS + p*16 + 8*lc));
                LDM4T(vl4, sptr(Vl + (c4*16 + lr)*AS + p*16 + 8*lc));
                mma_bf16(oacc[2*p],   ph, vh4[0], vh4[1]);
                mma_bf16(oacc[2*p],   ph, vl4[0], vl4[1]);
                mma_bf16(oacc[2*p],   pl, vh4[0], vh4[1]);
                mma_bf16(oacc[2*p+1], ph, vh4[2], vh4[3]);
                mma_bf16(oacc[2*p+1], ph, vl4[2], vl4[3]);
                mma_bf16(oacc[2*p+1], pl, vh4[2], vh4[3]);
            }
        }
        __syncthreads();
        buf ^= 1;
    }

    l0 += __shfl_xor_sync(0xffffffffu, l0, 1);
    l0 += __shfl_xor_sync(0xffffffffu, l0, 2);
    l1 += __shfl_xor_sync(0xffffffffu, l1, 1);
    l1 += __shfl_xor_sync(0xffffffffu, l1, 2);
    float inv0 = 1.f / l0, inv1 = 1.f / l1;

    int r0 = b*TT + q0 + mrow + g;
    #pragma unroll
    for (int nj = 0; nj < 8; nj++) {
        int c = h*64 + nj*8 + 2*tg;
        *(float2*)(o + (size_t)r0*DD + c) =
            make_float2(oacc[nj][0]*inv0, oacc[nj][1]*inv0);
        *(float2*)(o + (size_t)(r0+8)*DD + c) =
            make_float2(oacc[nj][2]*inv1, oacc[nj][3]*inv1);
    }
}

// ---------------- silu(f1)*f2 -> f1 ----------------
__global__ void silu_mul_kernel(float* __restrict__ f1,
                                const float* __restrict__ f2, int n4) {
    int i = blockIdx.x * blockDim.x + threadIdx.x;
    if (i < n4) {
        float4 a = ((float4*)f1)[i];
        float4 b = ((const float4*)f2)[i];
        a.x = a.x / (1.f + __expf(-a.x)) * b.x;
        a.y = a.y / (1.f + __expf(-a.y)) * b.y;
        a.z = a.z / (1.f + __expf(-a.z)) * b.z;
        a.w = a.w / (1.f + __expf(-a.w)) * b.w;
        ((float4*)f1)[i] = a;
    }
}

// ---------------- segment scan ----------------
__global__ void seg_scan_kernel(const int* __restrict__ tok,
                                int* __restrict__ seg) {
    int b = blockIdx.x;
    __shared__ int ssum[256];
    int t0 = threadIdx.x * 8;
    int loc[8];
    int run = 0;
    #pragma unroll
    for (int i = 0; i < 8; i++) {
        int tv = tok[b * TT + t0 + i];
        tv = min(max(tv, 0), 255);
        run += (int)((c_sepmask[tv >> 5] >> (tv & 31)) & 1u);
        loc[i] = run;
    }
    ssum[threadIdx.x] = run;
    __syncthreads();
    int val = run;
    for (int off = 1; off < 256; off <<= 1) {
        int add = (threadIdx.x >= off) ? ssum[threadIdx.x - off] : 0;
        __syncthreads();
        val += add;
        ssum[threadIdx.x] = val;
        __syncthreads();
    }
    int prefix = val - run;
    #pragma unroll
    for (int i = 0; i < 8; i++) seg[b * TT + t0 + i] = prefix + loc[i];
}

// ---------------- segment accumulate ----------------
__global__ void seg_acc_kernel(const float* __restrict__ xn,
                               const int* __restrict__ seg,
                               float* __restrict__ ssum,
                               float* __restrict__ scnt) {
    int row = blockIdx.x;
    int b = row >> 11;
    int s = seg[row] + b * (TT + 1);
    const float* xp = xn + (size_t)row * DD;
    float* sp = ssum + (size_t)s * DD;
    int i = threadIdx.x * 4;
    atomicAdd(&sp[i + 0], xp[i + 0]);
    atomicAdd(&sp[i + 1], xp[i + 1]);
    atomicAdd(&sp[i + 2], xp[i + 2]);
    atomicAdd(&sp[i + 3], xp[i + 3]);
    if (threadIdx.x == 0) atomicAdd(&scnt[s], 1.f);
}

// ---------------- final mix ----------------
__global__ void mix_kernel(const float* __restrict__ xn,
                           const int* __restrict__ seg,
                           const float* __restrict__ ssum,
                           const float* __restrict__ scnt,
                           float* __restrict__ out) {
    int row = blockIdx.x;
    int b = row >> 11;
    int s = seg[row] + b * (TT + 1);
    float cnt = fmaxf(scnt[s], 1.f);
    float w = (1.f - ALPHAF) / cnt;
    float4 xv = ((const float4*)(xn + (size_t)row * DD))[threadIdx.x];
    float4 sv = ((const float4*)(ssum + (size_t)s * DD))[threadIdx.x];
    float4 r;
    r.x = ALPHAF*xv.x + w*sv.x; r.y = ALPHAF*xv.y + w*sv.y;
    r.z = ALPHAF*xv.z + w*sv.z; r.w = ALPHAF*xv.w + w*sv.w;
    ((float4*)(out + (size_t)row * DD))[threadIdx.x] = r;
}

// ---------------- launch ----------------
extern "C" void kernel_launch(void* const* d_in, const int* in_sizes, int n_in,
                              void* d_out, int out_size) {
    const int*   tokens       = (const int*)  d_in[0];
    const float* embed_table  = (const float*)d_in[1];
    const float* attn_norm_w  = (const float*)d_in[2];
    const float* wq           = (const float*)d_in[3];
    const float* wk           = (const float*)d_in[4];
    const float* wv           = (const float*)d_in[5];
    const float* wo           = (const float*)d_in[6];
    const float* ffn_norm_w   = (const float*)d_in[7];
    const float* w1           = (const float*)d_in[8];
    const float* w2           = (const float*)d_in[9];
    const float* w3           = (const float*)d_in[10];
    const float* final_norm_w = (const float*)d_in[11];
    float* out = (float*)d_out;

    float *x, *h, *q, *k, *o, *xn, *f1, *f2, *ssum, *scnt;
    int* seg;
    __nv_bfloat16 *qh, *ql, *kh, *kl, *vh, *vl;
    cudaGetSymbolAddress((void**)&x,   g_x);
    cudaGetSymbolAddress((void**)&h,   g_h);
    cudaGetSymbolAddress((void**)&q,   g_q);
    cudaGetSymbolAddress((void**)&k,   g_k);
    cudaGetSymbolAddress((void**)&o,   g_o);
    cudaGetSymbolAddress((void**)&xn,  g_xn);
    cudaGetSymbolAddress((void**)&f1,  g_f1);
    cudaGetSymbolAddress((void**)&f2,  g_f2);
    cudaGetSymbolAddress((void**)&seg, g_seg);
    cudaGetSymbolAddress((void**)&ssum, g_segsum);
    cudaGetSymbolAddress((void**)&scnt, g_segcnt);
    cudaGetSymbolAddress((void**)&qh, g_qh);
    cudaGetSymbolAddress((void**)&ql, g_ql);
    cudaGetSymbolAddress((void**)&kh, g_kh);
    cudaGetSymbolAddress((void**)&kl, g_kl);
    cudaGetSymbolAddress((void**)&vh, g_vh);
    cudaGetSymbolAddress((void**)&vl, g_vl);

    cudaFuncSetAttribute(attn_kernel,
                         cudaFuncAttributeMaxDynamicSharedMemorySize, ATT_SMEM);

    embed_kernel<<<ROWS, 128>>>(tokens, embed_table, x);

    dim3 gD  (DD  / 128, ROWS / 128);       // (4, 64)
    dim3 gQKV(3 * DD / 128, ROWS / 128);    // (12, 64)
    dim3 gW12(2 * FFF / 128, ROWS / 128);   // (32, 64)
    dim3 gAtt(TT / 64, BB * HH);            // (32, 32)

    for (int l = 0; l < LL; l++) {
        size_t oD = (size_t)l * DD * DD, oF = (size_t)l * DD * FFF;
        rmsnorm_kernel<<<ROWS, 128>>>(x, attn_norm_w + l*DD, h);

        MatSet<3> msqkv;
        msqkv.B[0] = wq + oD; msqkv.B[1] = wk + oD; msqkv.B[2] = wv + oD;
        msqkv.C[0] = q;       msqkv.C[1] = k;       msqkv.C[2] = nullptr;
        gemm3qkv_kernel<<<gQKV, 256>>>(h, msqkv, vh, vl, DD, DD);

        ropecvt_kernel<<<ROWS, 256>>>(q, k, qh, ql, kh, kl);
        attn_kernel<<<gAtt, 128, ATT_SMEM>>>(qh, ql, kh, kl, vh, vl, o);
        gemm3_kernel<true ><<<gD, 256>>>(o, wo + oD, x, DD, DD);

        rmsnorm_kernel<<<ROWS, 128>>>(x, ffn_norm_w + l*DD, h);

        MatSet<2> msff;
        msff.B[0] = w1 + oF; msff.B[1] = w2 + oF;
        msff.C[0] = f1;      msff.C[1] = f2;
        gemm3m_kernel<2><<<gW12, 256>>>(h, msff, FFF, DD);

        int n4 = ROWS * FFF / 4;
        silu_mul_kernel<<<(n4 + 255)/256, 256>>>(f1, f2, n4);
        gemm3_kernel<true ><<<gD, 256>>>(f1, w3 + (size_t)l * FFF * DD, x, DD, FFF);
    }

    rmsnorm_kernel<<<ROWS, 128>>>(x, final_norm_w, xn);

    cudaMemsetAsync(ssum, 0, sizeof(float) * (size_t)NSEG * DD);
    cudaMemsetAsync(scnt, 0, sizeof(float) * NSEG);
    seg_scan_kernel<<<BB, 256>>>(tokens, seg);
    seg_acc_kernel<<<ROWS, 128>>>(xn, seg, ssum, scnt);
    mix_kernel<<<ROWS, 128>>>(xn, seg, ssum, scnt, out);
}